// round 10
// baseline (speedup 1.0000x reference)
#include <cuda_runtime.h>

#define THREADS 256
using ull = unsigned long long;

// ---- strides chosen so every hot LDS/STS is bank-conflict-free ----
constexpr int SA_STRIDE = 95, SA_SIZE = 64 * 95;   // attn plane (odd stride, row-window reads CF)
constexpr int SX_STRIDE = 69, SX_SIZE = 68 * 69;   // x plane, pad 2 (odd stride)
constexpr int ST_STRIDE = 66;                      // h-tmp: even => STS.64 aligned; col reads CF
constexpr int ST_FULL   = 94 * ST_STRIDE;          // rows -15..78 zero-padded: 6204
constexpr int UNION_SIZE  = (SX_SIZE > ST_FULL ? SX_SIZE : ST_FULL);      // 6204
constexpr int DATA_FLOATS = SA_SIZE + UNION_SIZE;  // 12284 (mult of 4 => tables 16B-aligned)
constexpr int P5_OFF = DATA_FLOATS;                // 5 rows x 6 shifted pairs = 60 floats
constexpr int PB_OFF = P5_OFF + 60;                // branch pair tables: 112 pairs = 224 floats
constexpr int BB_OFF = PB_OFF + 224;               // 7 bias pairs = 14 floats
constexpr int SMEM_FLOATS = BB_OFF + 14;           // 12582 floats = 50328 B (dynamic smem)

// pair-table float offsets within PB: H7=0, V7=16, H15=32, V15=64, H31=96(+128), V31=160(+192)

__device__ __forceinline__ ull ldpair(const float* p) { return *(const ull*)p; }
__device__ __forceinline__ void fma2(ull& acc, ull a, ull b) {
    asm("fma.rn.f32x2 %0, %1, %2, %0;" : "+l"(acc) : "l"(a), "l"(b));
}
__device__ __forceinline__ float2 up2(ull d) {
    float2 r; asm("mov.b64 {%0, %1}, %2;" : "=f"(r.x), "=f"(r.y) : "l"(d)); return r;
}
__device__ __forceinline__ ull dup(float v) {
    ull d; asm("mov.b64 %0, {%1, %1};" : "=l"(d) : "f"(v)); return d;
}

// Preload NP weight pairs (NP even) with LDS.128 broadcast: 2 pairs per instruction.
template<int NP>
__device__ __forceinline__ void loadpairs(ull* w2, const float* __restrict__ ptab) {
#pragma unroll
    for (int t = 0; t < NP; t += 2) {
        const ulonglong2 p = *(const ulonglong2*)(ptab + 2 * t);
        w2[t] = p.x; w2[t + 1] = p.y;
    }
}

// Sliding-window sweep over tap range [T0,T1), weights register-resident.
// acc2[q] = (out_{2q}, out_{2q+1}); tap t feeds q at window step m = t + 2q.
// Chunked: 8 independent window loads batched (real MLP=8 now that regs allow it),
// then 8 dup+FMA2 groups covered by the previous chunk's tail.
template<int T0, int T1, class LD>
__device__ __forceinline__ void sweep16(ull acc2[8], const ull* w2, LD ld)
{
    constexpr int ME = T1 + 14;      // steps m = T0 .. ME-1
#pragma unroll
    for (int m0 = T0; m0 < ME; m0 += 8) {
        float v[8];
#pragma unroll
        for (int u = 0; u < 8; u++)
            if (m0 + u < ME) v[u] = ld(m0 + u);
#pragma unroll
        for (int u = 0; u < 8; u++) {
            const int m = m0 + u;
            if (m < ME) {
                const ull vv = dup(v[u]);
#pragma unroll
                for (int q = 0; q < 8; q++) {
                    const int t = m - 2 * q;
                    if (t >= T0 && t < T1) fma2(acc2[q], vv, w2[t - T0]);
                }
            }
        }
    }
}

template<int K, class LD>
__device__ __forceinline__ void runconv(ull acc2[8], const float* __restrict__ ptab, LD ld)
{
    if constexpr (K == 31) {
        // two 16-tap sweeps, weights fully preloaded (no in-loop weight dependency)
        { ull w2[16]; loadpairs<16>(w2, ptab);      sweep16<0, 16>(acc2, w2, ld);  }
        { ull w2[16]; loadpairs<16>(w2, ptab + 32); sweep16<16, 32>(acc2, w2, ld); }
    } else {
        ull w2[K + 1];
        loadpairs<K + 1>(w2, ptab);
        sweep16<0, K + 1>(acc2, w2, ld);
    }
}

// Horizontal 1xK: s_a -> s_t (rows 0..63 only; pad rows persist). STS.64 stores.
template<int K>
__device__ __forceinline__ void hbranch(const float* __restrict__ s_a,
                                        float* __restrict__ s_t,
                                        const float* __restrict__ ptab,
                                        ull bias2, int h, int col0)
{
    ull acc2[8];
#pragma unroll
    for (int q = 0; q < 8; q++) acc2[q] = bias2;
    const float* sr = s_a + h * SA_STRIDE + 15 + col0 - K / 2;
    runconv<K>(acc2, ptab, [&](int m) { return sr[m]; });
    float2* st = (float2*)(s_t + h * ST_STRIDE + col0);   // even addr => 8B aligned
#pragma unroll
    for (int q = 0; q < 8; q++) st[q] = up2(acc2[q]);
}

// Vertical Kx1: s_t (zero-padded rows) -> global. No predication: pure LDS [R+imm].
template<int K>
__device__ __forceinline__ void vbranch(const float* __restrict__ s_t,
                                        const float* __restrict__ ptab,
                                        ull bias2,
                                        float* __restrict__ osec, int col, int r0)
{
    ull acc2[8];
#pragma unroll
    for (int q = 0; q < 8; q++) acc2[q] = bias2;
    const float* sv = s_t + (r0 - K / 2) * ST_STRIDE + col;   // rows >= -15: in pad
    runconv<K>(acc2, ptab, [&](int m) { return sv[m * ST_STRIDE]; });
#pragma unroll
    for (int q = 0; q < 8; q++) {
        const float2 v = up2(acc2[q]);
        osec[(r0 + 2 * q) * 64 + col] = v.x;
        osec[(r0 + 2 * q + 1) * 64 + col] = v.y;
    }
}

__global__ __launch_bounds__(THREADS, 3)   // 84 regs: lets the MLP=8 batches materialize
void lka_kernel(const float* __restrict__ x,
                const float* __restrict__ w0,  const float* __restrict__ b0,
                const float* __restrict__ w01, const float* __restrict__ b01,
                const float* __restrict__ w02, const float* __restrict__ b02,
                const float* __restrict__ w11, const float* __restrict__ b11,
                const float* __restrict__ w12, const float* __restrict__ b12,
                const float* __restrict__ w21, const float* __restrict__ b21,
                const float* __restrict__ w22, const float* __restrict__ b22,
                float* __restrict__ out)
{
    extern __shared__ __align__(16) float sm[];
    float* s_a = sm;
    float* s_x = sm + SA_SIZE;                      // union
    float* s_t = sm + SA_SIZE + 15 * ST_STRIDE;     // union, rows -15..78 padded

    const int tid = threadIdx.x;
    const int bc  = blockIdx.x;
    const int c   = bc & 127;
    const int b   = bc >> 7;

    const int h    = tid & 63;
    const int col0 = (tid >> 6) << 4;

    const float* xp = x + (long)bc * 4096;
    float* outb = out + (long)b * (640 * 4096) + (long)c * 4096;

    // ================= P0: x fill + s_a/s_x margins + weight tables =================
    {
        const float4* xp4 = (const float4*)xp;
        float4* out4 = (float4*)outb;
#pragma unroll
        for (int k = 0; k < 4; k++) {
            const int i4 = tid + k * THREADS;
            const float4 v = xp4[i4];
            out4[i4] = v;
            const int i = i4 << 2;
            float* dst = &s_x[((i >> 6) + 2) * SX_STRIDE + (i & 63) + 2];
            dst[0] = v.x; dst[1] = v.y; dst[2] = v.z; dst[3] = v.w;
        }
    }
    for (int i = tid; i < 2048; i += THREADS) {          // s_a cols [0,16) U [79,95)
        const int r = i >> 5, m = i & 31;
        s_a[r * SA_STRIDE + (m < 16 ? m : 63 + m)] = 0.0f;
    }
    for (int i = tid; i < 276; i += THREADS) {           // s_x rows {0,1,66,67}
        const int r = i / 69, cc = i % 69;
        s_x[(r < 2 ? r : 64 + r) * SX_STRIDE + cc] = 0.0f;
    }
    for (int i = tid; i < 320; i += THREADS) {           // s_x cols {0,1,66,67,68}, rows [2,66)
        const int r = 2 + i / 5, cc5 = i % 5;
        s_x[r * SX_STRIDE + (cc5 < 2 ? cc5 : 64 + cc5)] = 0.0f;
    }
    if (tid < 112) {                                     // pair tables P[t]=(w_t,w_{t-1})
        int t; int K; const float* w;
        if (tid < 8)       { t = tid;      K = 7;  w = w01 + c * 7;  }
        else if (tid < 16) { t = tid - 8;  K = 7;  w = w02 + c * 7;  }
        else if (tid < 32) { t = tid - 16; K = 15; w = w11 + c * 15; }
        else if (tid < 48) { t = tid - 32; K = 15; w = w12 + c * 15; }
        else if (tid < 80) { t = tid - 48; K = 31; w = w21 + c * 31; }
        else               { t = tid - 80; K = 31; w = w22 + c * 31; }
        sm[PB_OFF + 2 * tid]     = (t < K) ? __ldg(w + t)     : 0.0f;
        sm[PB_OFF + 2 * tid + 1] = (t > 0) ? __ldg(w + t - 1) : 0.0f;
    } else if (tid < 142) {                              // 5x5: 5 rows x 6 pairs
        const int j = tid - 112, r = j / 6, t = j % 6;
        const float* w = w0 + c * 25 + r * 5;
        sm[P5_OFF + 2 * j]     = (t < 5) ? __ldg(w + t)     : 0.0f;
        sm[P5_OFF + 2 * j + 1] = (t > 0) ? __ldg(w + t - 1) : 0.0f;
    } else if (tid < 149) {                              // bias pairs
        const int j = tid - 142;
        const float* bp = (j == 0) ? b0 : (j == 1) ? b01 : (j == 2) ? b02
                        : (j == 3) ? b11 : (j == 4) ? b12 : (j == 5) ? b21 : b22;
        const float v = __ldg(bp + c);
        sm[BB_OFF + 2 * j] = v; sm[BB_OFF + 2 * j + 1] = v;
    }
    __syncthreads();

    // ================= P1: 5x5 depthwise conv -> s_a ================================
    {
        ull acc2[8];
        const ull bias2 = ldpair(sm + BB_OFF);
#pragma unroll
        for (int q = 0; q < 8; q++) acc2[q] = bias2;
#pragma unroll
        for (int r = 0; r < 5; r++) {
            const float* srow = s_x + (h + r) * SX_STRIDE + col0;
            ull w2[6];
            loadpairs<6>(w2, sm + P5_OFF + r * 12);
            sweep16<0, 6>(acc2, w2, [&](int m) { return srow[m]; });
        }
        float* sa = s_a + h * SA_STRIDE + 15 + col0;
#pragma unroll
        for (int q = 0; q < 8; q++) {
            const float2 v = up2(acc2[q]);
            sa[2 * q] = v.x; sa[2 * q + 1] = v.y;
        }
    }
    __syncthreads();   // 5x5 done; s_x (union) now dead => s_t region writable

    const float* PB = sm + PB_OFF;
    const float* BB = sm + BB_OFF;

    // ================= P2: attn copy + s_t pad zero + h7 -> s_t =====================
    {
        // zero the 30 pad rows of s_t once (persist: h-stores touch rows 0..63 only)
        for (int i = tid; i < 30 * ST_STRIDE; i += THREADS) {
            const int r = i / ST_STRIDE, cc = i % ST_STRIDE;
            s_t[((r < 15) ? (r - 15) : (r + 49)) * ST_STRIDE + cc] = 0.0f;
        }
        float* out1 = outb + 128 * 4096;
#pragma unroll
        for (int k = 0; k < 16; k++) {
            const int i = tid + k * THREADS;
            out1[i] = s_a[(i >> 6) * SA_STRIDE + 15 + (i & 63)];
        }
        hbranch<7>(s_a, s_t, PB + 0, ldpair(BB + 2), h, col0);
    }
    __syncthreads();

    // ================= P3..P7: v/h ladder ===========================================
    vbranch<7>(s_t, PB + 16, ldpair(BB + 4), outb + 2 * 128 * 4096, h, col0);
    __syncthreads();
    hbranch<15>(s_a, s_t, PB + 32, ldpair(BB + 6), h, col0);
    __syncthreads();
    vbranch<15>(s_t, PB + 64, ldpair(BB + 8), outb + 3 * 128 * 4096, h, col0);
    __syncthreads();
    hbranch<31>(s_a, s_t, PB + 96, ldpair(BB + 10), h, col0);
    __syncthreads();
    vbranch<31>(s_t, PB + 160, ldpair(BB + 12), outb + 4 * 128 * 4096, h, col0);
}

extern "C" void kernel_launch(void* const* d_in, const int* in_sizes, int n_in,
                              void* d_out, int out_size)
{
    constexpr int SMEM_BYTES = SMEM_FLOATS * 4;   // 50328 B > 48 KB => opt-in
    static int attr_done = 0;                     // idempotent attribute set (not a stream op)
    if (!attr_done) {
        cudaFuncSetAttribute(lka_kernel, cudaFuncAttributeMaxDynamicSharedMemorySize, SMEM_BYTES);
        attr_done = 1;
    }
    lka_kernel<<<32 * 128, THREADS, SMEM_BYTES>>>(
        (const float*)d_in[0],
        (const float*)d_in[1],  (const float*)d_in[2],
        (const float*)d_in[3],  (const float*)d_in[4],
        (const float*)d_in[5],  (const float*)d_in[6],
        (const float*)d_in[7],  (const float*)d_in[8],
        (const float*)d_in[9],  (const float*)d_in[10],
        (const float*)d_in[11], (const float*)d_in[12],
        (const float*)d_in[13], (const float*)d_in[14],
        (float*)d_out);
}

// round 11
// speedup vs baseline: 1.0411x; 1.0411x over previous
#include <cuda_runtime.h>

#define THREADS 256
using ull = unsigned long long;

// ---- strides chosen so every hot LDS/STS is bank-conflict-free ----
constexpr int SA_STRIDE = 95, SA_SIZE = 64 * 95;   // attn plane (odd stride)
constexpr int SX_STRIDE = 69, SX_SIZE = 68 * 69;   // x plane, pad 2 (odd stride)
constexpr int ST_STRIDE = 65;                      // h-tmp, rows -15..78 zero-padded
constexpr int ST_FULL   = 94 * ST_STRIDE;          // 6110
constexpr int UNION_SIZE  = (SX_SIZE > ST_FULL ? SX_SIZE : ST_FULL) + 2;  // 6112
constexpr int DATA_FLOATS = SA_SIZE + UNION_SIZE;  // 12192 (mult of 4 => tables 16B-aligned)
constexpr int P5_OFF = DATA_FLOATS;                // 5 dx-cols x 6 vertical pairs = 60 floats
constexpr int PB_OFF = P5_OFF + 60;                // branch pair tables: 112 pairs = 224 floats
constexpr int BB_OFF = PB_OFF + 224;               // 7 bias pairs = 14 floats
constexpr int SMEM_FLOATS = BB_OFF + 14;           // 12490 floats = 49960 B (dynamic smem)

// pair-table float offsets within PB: H7=0, V7=16, H15=32, V15=64, H31=96, V31=160

__device__ __forceinline__ ull ldpair(const float* p) { return *(const ull*)p; }
__device__ __forceinline__ void fma2(ull& acc, ull a, ull b) {
    asm("fma.rn.f32x2 %0, %1, %2, %0;" : "+l"(acc) : "l"(a), "l"(b));
}
__device__ __forceinline__ float2 up2(ull d) {
    float2 r; asm("mov.b64 {%0, %1}, %2;" : "=f"(r.x), "=f"(r.y) : "l"(d)); return r;
}
__device__ __forceinline__ ull dup(float v) {
    ull d; asm("mov.b64 %0, {%1, %1};" : "=l"(d) : "f"(v)); return d;
}

// Preload NP weight pairs (NP even) with LDS.128 broadcast: 2 pairs per instruction.
template<int NP>
__device__ __forceinline__ void loadpairs(ull* w2, const float* __restrict__ ptab) {
#pragma unroll
    for (int t = 0; t < NP; t += 2) {
        const ulonglong2 p = *(const ulonglong2*)(ptab + 2 * t);
        w2[t] = p.x; w2[t + 1] = p.y;
    }
}

// Streaming sliding-window: 16 outputs (8 adjacent pairs), weights register-resident.
// acc2[q] = (out_{2q}, out_{2q+1}); tap pair t feeds q at window step m = t + 2q.
template<int NP, class LD>
__device__ __forceinline__ void conv16_reg(ull acc2[8], const ull* w2, LD ld)
{
#pragma unroll
    for (int m = 0; m < NP + 14; m++) {
        const ull vv = dup(ld(m));
#pragma unroll
        for (int q = 0; q < 8; q++) {
            const int t = m - 2 * q;
            if (t >= 0 && t < NP) fma2(acc2[q], vv, w2[t]);
        }
    }
}

// K=31 (NP=32): rotating 16-slot pair buffer, refilled 2 pairs per LDS.128.
// Slot liveness: pair t last used at step t+14; overwritten at t+15/t+16 => safe.
template<class LD>
__device__ __forceinline__ void conv16_rot32(ull acc2[8], const float* __restrict__ ptab, LD ld)
{
    ull wb[16];
#pragma unroll
    for (int m = 0; m < 46; m++) {
        if (m < 32 && !(m & 1)) {
            const ulonglong2 p = *(const ulonglong2*)(ptab + 2 * m);
            wb[m & 15] = p.x; wb[(m + 1) & 15] = p.y;
        }
        const ull vv = dup(ld(m));
#pragma unroll
        for (int q = 0; q < 8; q++) {
            const int t = m - 2 * q;
            if (t >= 0 && t < 32) fma2(acc2[q], vv, wb[t & 15]);
        }
    }
}

template<int K, class LD>
__device__ __forceinline__ void runconv(ull acc2[8], const float* __restrict__ ptab, LD ld)
{
    if constexpr (K == 31) {
        conv16_rot32(acc2, ptab, ld);
    } else {
        ull w2[K + 1];
        loadpairs<K + 1>(w2, ptab);
        conv16_reg<K + 1>(acc2, w2, ld);
    }
}

// Horizontal 1xK: s_a -> s_t (rows 0..63 only; pad rows persist). All CF.
template<int K>
__device__ __forceinline__ void hbranch(const float* __restrict__ s_a,
                                        float* __restrict__ s_t,
                                        const float* __restrict__ ptab,
                                        ull bias2, int h, int col0)
{
    ull acc2[8];
#pragma unroll
    for (int q = 0; q < 8; q++) acc2[q] = bias2;
    const float* sr = s_a + h * SA_STRIDE + 15 + col0 - K / 2;
    runconv<K>(acc2, ptab, [&](int m) { return sr[m]; });
    float* st = s_t + h * ST_STRIDE + col0;
#pragma unroll
    for (int q = 0; q < 8; q++) {
        const float2 v = up2(acc2[q]);
        st[2 * q] = v.x; st[2 * q + 1] = v.y;
    }
}

// Vertical Kx1: s_t (zero-padded rows) -> global. No predication: pure LDS [R+imm].
template<int K>
__device__ __forceinline__ void vbranch(const float* __restrict__ s_t,
                                        const float* __restrict__ ptab,
                                        ull bias2,
                                        float* __restrict__ osec, int col, int r0)
{
    ull acc2[8];
#pragma unroll
    for (int q = 0; q < 8; q++) acc2[q] = bias2;
    const float* sv = s_t + (r0 - K / 2) * ST_STRIDE + col;   // rows >= -15: in pad
    runconv<K>(acc2, ptab, [&](int m) { return sv[m * ST_STRIDE]; });
#pragma unroll
    for (int q = 0; q < 8; q++) {
        const float2 v = up2(acc2[q]);
        osec[(r0 + 2 * q) * 64 + col] = v.x;
        osec[(r0 + 2 * q + 1) * 64 + col] = v.y;
    }
}

__global__ __launch_bounds__(THREADS, 4)
void lka_kernel(const float* __restrict__ x,
                const float* __restrict__ w0,  const float* __restrict__ b0,
                const float* __restrict__ w01, const float* __restrict__ b01,
                const float* __restrict__ w02, const float* __restrict__ b02,
                const float* __restrict__ w11, const float* __restrict__ b11,
                const float* __restrict__ w12, const float* __restrict__ b12,
                const float* __restrict__ w21, const float* __restrict__ b21,
                const float* __restrict__ w22, const float* __restrict__ b22,
                float* __restrict__ out)
{
    extern __shared__ __align__(16) float sm[];
    float* s_a = sm;
    float* s_x = sm + SA_SIZE;                      // union
    float* s_t = sm + SA_SIZE + 15 * ST_STRIDE;     // union, rows -15..78 padded

    const int tid = threadIdx.x;
    const int bc  = blockIdx.x;
    const int c   = bc & 127;
    const int b   = bc >> 7;

    const int h    = tid & 63;              // row for h-passes / col for v-passes
    const int col0 = (tid >> 6) << 4;

    const float* xp = x + (long)bc * 4096;
    float* outb = out + (long)b * (640 * 4096) + (long)c * 4096;

    // ================= P0: x fill + s_a/s_x margins + weight tables =================
    {
        const float4* xp4 = (const float4*)xp;
        float4* out4 = (float4*)outb;
#pragma unroll
        for (int k = 0; k < 4; k++) {
            const int i4 = tid + k * THREADS;
            const float4 v = xp4[i4];
            out4[i4] = v;
            const int i = i4 << 2;
            float* dst = &s_x[((i >> 6) + 2) * SX_STRIDE + (i & 63) + 2];
            dst[0] = v.x; dst[1] = v.y; dst[2] = v.z; dst[3] = v.w;
        }
    }
    for (int i = tid; i < 2048; i += THREADS) {          // s_a cols [0,16) U [79,95)
        const int r = i >> 5, m = i & 31;
        s_a[r * SA_STRIDE + (m < 16 ? m : 63 + m)] = 0.0f;
    }
    for (int i = tid; i < 276; i += THREADS) {           // s_x rows {0,1,66,67}
        const int r = i / 69, cc = i % 69;
        s_x[(r < 2 ? r : 64 + r) * SX_STRIDE + cc] = 0.0f;
    }
    for (int i = tid; i < 320; i += THREADS) {           // s_x cols {0,1,66,67,68}, rows [2,66)
        const int r = 2 + i / 5, cc5 = i % 5;
        s_x[r * SX_STRIDE + (cc5 < 2 ? cc5 : 64 + cc5)] = 0.0f;
    }
    if (tid < 112) {                                     // pair tables P[t]=(w_t,w_{t-1})
        int t; int K; const float* w;
        if (tid < 8)       { t = tid;      K = 7;  w = w01 + c * 7;  }
        else if (tid < 16) { t = tid - 8;  K = 7;  w = w02 + c * 7;  }
        else if (tid < 32) { t = tid - 16; K = 15; w = w11 + c * 15; }
        else if (tid < 48) { t = tid - 32; K = 15; w = w12 + c * 15; }
        else if (tid < 80) { t = tid - 48; K = 31; w = w21 + c * 31; }
        else               { t = tid - 80; K = 31; w = w22 + c * 31; }
        sm[PB_OFF + 2 * tid]     = (t < K) ? __ldg(w + t)     : 0.0f;
        sm[PB_OFF + 2 * tid + 1] = (t > 0) ? __ldg(w + t - 1) : 0.0f;
    } else if (tid < 142) {
        // 5x5 table, col-major conv: for dx (horizontal tap), vertical pairs
        // P5[dx][t] = (w[t][dx], w[t-1][dx]), w row-major in w0[c*25 + row*5 + col]
        const int j = tid - 112, dx = j / 6, t = j % 6;
        const float* w = w0 + c * 25 + dx;
        sm[P5_OFF + 2 * j]     = (t < 5) ? __ldg(w + t * 5)       : 0.0f;
        sm[P5_OFF + 2 * j + 1] = (t > 0) ? __ldg(w + (t - 1) * 5) : 0.0f;
    } else if (tid < 149) {                              // bias pairs
        const int j = tid - 142;
        const float* bp = (j == 0) ? b0 : (j == 1) ? b01 : (j == 2) ? b02
                        : (j == 3) ? b11 : (j == 4) ? b12 : (j == 5) ? b21 : b22;
        const float v = __ldg(bp + c);
        sm[BB_OFF + 2 * j] = v; sm[BB_OFF + 2 * j + 1] = v;
    }
    __syncthreads();

    // ====== P1: 5x5 depthwise conv, COL-MAJOR: thread = col, 16 rows.  =============
    // Outputs land in (row, col) orientation with lanes = consecutive cols, so attn
    // section 1 is stored DIRECTLY to global (coalesced STG) — no smem copy phase.
    {
        ull acc2[8];
        const ull bias2 = ldpair(sm + BB_OFF);
#pragma unroll
        for (int q = 0; q < 8; q++) acc2[q] = bias2;
        const int col = h;         // lane-contiguous
        const int r0  = col0;      // 16-row slab
#pragma unroll
        for (int dx = 0; dx < 5; dx++) {
            ull w2[6];
            loadpairs<6>(w2, sm + P5_OFF + dx * 12);
            // window row i lives at padded s_x row r0+i; horizontal tap dx-2 at col+dx
            const float* swin = s_x + r0 * SX_STRIDE + col + dx;
            conv16_reg<6>(acc2, w2, [&](int m) { return swin[m * SX_STRIDE]; });
        }
        float* sa   = s_a + 15 + col;
        float* out1 = outb + 128 * 4096 + col;
#pragma unroll
        for (int q = 0; q < 8; q++) {
            const float2 v = up2(acc2[q]);
            sa[(r0 + 2 * q) * SA_STRIDE]       = v.x;   // CF STS (lane stride 1)
            sa[(r0 + 2 * q + 1) * SA_STRIDE]   = v.y;
            out1[(r0 + 2 * q) * 64]            = v.x;   // coalesced STG
            out1[(r0 + 2 * q + 1) * 64]        = v.y;
        }
    }
    __syncthreads();   // 5x5 done; s_x (union) now dead => s_t region writable

    const float* PB = sm + PB_OFF;
    const float* BB = sm + BB_OFF;

    // ================= P2: s_t pad zero + h7 -> s_t =================================
    {
        // zero the 30 pad rows of s_t once (persist: h-stores touch rows 0..63 only)
        for (int i = tid; i < 30 * ST_STRIDE; i += THREADS) {
            const int r = i / ST_STRIDE, cc = i % ST_STRIDE;
            s_t[((r < 15) ? (r - 15) : (r + 49)) * ST_STRIDE + cc] = 0.0f;
        }
        hbranch<7>(s_a, s_t, PB + 0, ldpair(BB + 2), h, col0);
    }
    __syncthreads();

    // ================= P3..P6: v/h ladder ===========================================
    vbranch<7>(s_t, PB + 16, ldpair(BB + 4), outb + 2 * 128 * 4096, h, col0);
    __syncthreads();
    hbranch<15>(s_a, s_t, PB + 32, ldpair(BB + 6), h, col0);
    __syncthreads();
    vbranch<15>(s_t, PB + 64, ldpair(BB + 8), outb + 3 * 128 * 4096, h, col0);
    __syncthreads();
    hbranch<31>(s_a, s_t, PB + 96, ldpair(BB + 10), h, col0);
    __syncthreads();
    vbranch<31>(s_t, PB + 160, ldpair(BB + 12), outb + 4 * 128 * 4096, h, col0);
}

extern "C" void kernel_launch(void* const* d_in, const int* in_sizes, int n_in,
                              void* d_out, int out_size)
{
    constexpr int SMEM_BYTES = SMEM_FLOATS * 4;   // 49960 B > 48 KB => opt-in
    static int attr_done = 0;                     // idempotent attribute set (not a stream op)
    if (!attr_done) {
        cudaFuncSetAttribute(lka_kernel, cudaFuncAttributeMaxDynamicSharedMemorySize, SMEM_BYTES);
        attr_done = 1;
    }
    lka_kernel<<<32 * 128, THREADS, SMEM_BYTES>>>(
        (const float*)d_in[0],
        (const float*)d_in[1],  (const float*)d_in[2],
        (const float*)d_in[3],  (const float*)d_in[4],
        (const float*)d_in[5],  (const float*)d_in[6],
        (const float*)d_in[7],  (const float*)d_in[8],
        (const float*)d_in[9],  (const float*)d_in[10],
        (const float*)d_in[11], (const float*)d_in[12],
        (const float*)d_in[13], (const float*)d_in[14],
        (float*)d_out);
}

// round 12
// speedup vs baseline: 1.0414x; 1.0003x over previous
#include <cuda_runtime.h>

#define THREADS 256
using ull = unsigned long long;

// ---- strides chosen so every hot LDS/STS is bank-conflict-free ----
constexpr int SA_STRIDE = 95, SA_SIZE = 64 * 95;   // attn plane (odd stride)
constexpr int SX_STRIDE = 69, SX_SIZE = 68 * 69;   // x plane, pad 2 (odd stride)
constexpr int ST_STRIDE = 65;                      // h-tmp, rows -15..78 zero-padded
constexpr int ST_FULL   = 94 * ST_STRIDE;          // 6110
constexpr int UNION_SIZE  = (SX_SIZE > ST_FULL ? SX_SIZE : ST_FULL) + 2;  // 6112
constexpr int DATA_FLOATS = SA_SIZE + UNION_SIZE;  // 12192 (mult of 4 => tables 16B-aligned)
constexpr int P5_OFF = DATA_FLOATS;                // 5 dx-cols x 6 vertical pairs = 60 floats
constexpr int PB_OFF = P5_OFF + 60;                // branch pair tables: 112 pairs = 224 floats
constexpr int BB_OFF = PB_OFF + 224;               // 7 bias pairs = 14 floats
constexpr int SMEM_FLOATS = BB_OFF + 14;           // 12490 floats = 49960 B (dynamic smem)

// pair-table float offsets within PB: H7=0, V7=16, H15=32, V15=64, H31=96, V31=160

__device__ __forceinline__ ull ldpair(const float* p) { return *(const ull*)p; }
__device__ __forceinline__ void fma2(ull& acc, ull a, ull b) {
    asm("fma.rn.f32x2 %0, %1, %2, %0;" : "+l"(acc) : "l"(a), "l"(b));
}
__device__ __forceinline__ float2 up2(ull d) {
    float2 r; asm("mov.b64 {%0, %1}, %2;" : "=f"(r.x), "=f"(r.y) : "l"(d)); return r;
}
__device__ __forceinline__ ull dup(float v) {
    ull d; asm("mov.b64 %0, {%1, %1};" : "=l"(d) : "f"(v)); return d;
}

// Preload NP weight pairs (NP even) with LDS.128 broadcast: 2 pairs per instruction.
template<int NP>
__device__ __forceinline__ void loadpairs(ull* w2, const float* __restrict__ ptab) {
#pragma unroll
    for (int t = 0; t < NP; t += 2) {
        const ulonglong2 p = *(const ulonglong2*)(ptab + 2 * t);
        w2[t] = p.x; w2[t + 1] = p.y;
    }
}

// Streaming sliding-window: 16 outputs (8 adjacent pairs), weights register-resident.
// acc2[q] = (out_{2q}, out_{2q+1}); tap pair t feeds q at window step m = t + 2q.
template<int NP, class LD>
__device__ __forceinline__ void conv16_reg(ull acc2[8], const ull* w2, LD ld)
{
#pragma unroll
    for (int m = 0; m < NP + 14; m++) {
        const ull vv = dup(ld(m));
#pragma unroll
        for (int q = 0; q < 8; q++) {
            const int t = m - 2 * q;
            if (t >= 0 && t < NP) fma2(acc2[q], vv, w2[t]);
        }
    }
}

// K=31 (NP=32): rotating 16-slot pair buffer, refilled 2 pairs per LDS.128.
// Slot liveness: pair t last used at step t+14; overwritten at t+15/t+16 => safe.
template<class LD>
__device__ __forceinline__ void conv16_rot32(ull acc2[8], const float* __restrict__ ptab, LD ld)
{
    ull wb[16];
#pragma unroll
    for (int m = 0; m < 46; m++) {
        if (m < 32 && !(m & 1)) {
            const ulonglong2 p = *(const ulonglong2*)(ptab + 2 * m);
            wb[m & 15] = p.x; wb[(m + 1) & 15] = p.y;
        }
        const ull vv = dup(ld(m));
#pragma unroll
        for (int q = 0; q < 8; q++) {
            const int t = m - 2 * q;
            if (t >= 0 && t < 32) fma2(acc2[q], vv, wb[t & 15]);
        }
    }
}

template<int K, class LD>
__device__ __forceinline__ void runconv(ull acc2[8], const float* __restrict__ ptab, LD ld)
{
    if constexpr (K == 31) {
        conv16_rot32(acc2, ptab, ld);
    } else {
        ull w2[K + 1];
        loadpairs<K + 1>(w2, ptab);
        conv16_reg<K + 1>(acc2, w2, ld);
    }
}

// Horizontal 1xK: s_a -> s_t (rows 0..63 only; pad rows persist). All CF.
template<int K>
__device__ __forceinline__ void hbranch(const float* __restrict__ s_a,
                                        float* __restrict__ s_t,
                                        const float* __restrict__ ptab,
                                        ull bias2, int h, int col0)
{
    ull acc2[8];
#pragma unroll
    for (int q = 0; q < 8; q++) acc2[q] = bias2;
    const float* sr = s_a + h * SA_STRIDE + 15 + col0 - K / 2;
    runconv<K>(acc2, ptab, [&](int m) { return sr[m]; });
    float* st = s_t + h * ST_STRIDE + col0;
#pragma unroll
    for (int q = 0; q < 8; q++) {
        const float2 v = up2(acc2[q]);
        st[2 * q] = v.x; st[2 * q + 1] = v.y;
    }
}

// Vertical Kx1: s_t (zero-padded rows) -> global. No predication: pure LDS [R+imm].
template<int K>
__device__ __forceinline__ void vbranch(const float* __restrict__ s_t,
                                        const float* __restrict__ ptab,
                                        ull bias2,
                                        float* __restrict__ osec, int col, int r0)
{
    ull acc2[8];
#pragma unroll
    for (int q = 0; q < 8; q++) acc2[q] = bias2;
    const float* sv = s_t + (r0 - K / 2) * ST_STRIDE + col;   // rows >= -15: in pad
    runconv<K>(acc2, ptab, [&](int m) { return sv[m * ST_STRIDE]; });
#pragma unroll
    for (int q = 0; q < 8; q++) {
        const float2 v = up2(acc2[q]);
        osec[(r0 + 2 * q) * 64 + col] = v.x;
        osec[(r0 + 2 * q + 1) * 64 + col] = v.y;
    }
}

__global__ __launch_bounds__(THREADS, 4)
void lka_kernel(const float* __restrict__ x,
                const float* __restrict__ w0,  const float* __restrict__ b0,
                const float* __restrict__ w01, const float* __restrict__ b01,
                const float* __restrict__ w02, const float* __restrict__ b02,
                const float* __restrict__ w11, const float* __restrict__ b11,
                const float* __restrict__ w12, const float* __restrict__ b12,
                const float* __restrict__ w21, const float* __restrict__ b21,
                const float* __restrict__ w22, const float* __restrict__ b22,
                float* __restrict__ out)
{
    extern __shared__ __align__(16) float sm[];
    float* s_a = sm;
    float* s_x = sm + SA_SIZE;                      // union
    float* s_t = sm + SA_SIZE + 15 * ST_STRIDE;     // union, rows -15..78 padded

    const int tid = threadIdx.x;
    const int bc  = blockIdx.x;
    const int c   = bc & 127;
    const int b   = bc >> 7;

    const int h    = tid & 63;              // row for h-passes / col for v-passes
    const int col0 = (tid >> 6) << 4;

    const float* xp = x + (long)bc * 4096;
    float* outb = out + (long)b * (640 * 4096) + (long)c * 4096;

    // ================= P0: x fill + s_a/s_x margins + weight tables =================
    {
        const float4* xp4 = (const float4*)xp;
        float4* out4 = (float4*)outb;
#pragma unroll
        for (int k = 0; k < 4; k++) {
            const int i4 = tid + k * THREADS;
            const float4 v = xp4[i4];
            out4[i4] = v;
            const int i = i4 << 2;
            float* dst = &s_x[((i >> 6) + 2) * SX_STRIDE + (i & 63) + 2];
            dst[0] = v.x; dst[1] = v.y; dst[2] = v.z; dst[3] = v.w;
        }
    }
    for (int i = tid; i < 2048; i += THREADS) {          // s_a cols [0,16) U [79,95)
        const int r = i >> 5, m = i & 31;
        s_a[r * SA_STRIDE + (m < 16 ? m : 63 + m)] = 0.0f;
    }
    for (int i = tid; i < 276; i += THREADS) {           // s_x rows {0,1,66,67}
        const int r = i / 69, cc = i % 69;
        s_x[(r < 2 ? r : 64 + r) * SX_STRIDE + cc] = 0.0f;
    }
    for (int i = tid; i < 320; i += THREADS) {           // s_x cols {0,1,66,67,68}, rows [2,66)
        const int r = 2 + i / 5, cc5 = i % 5;
        s_x[r * SX_STRIDE + (cc5 < 2 ? cc5 : 64 + cc5)] = 0.0f;
    }
    if (tid < 112) {                                     // pair tables P[t]=(w_t,w_{t-1})
        int t; int K; const float* w;
        if (tid < 8)       { t = tid;      K = 7;  w = w01 + c * 7;  }
        else if (tid < 16) { t = tid - 8;  K = 7;  w = w02 + c * 7;  }
        else if (tid < 32) { t = tid - 16; K = 15; w = w11 + c * 15; }
        else if (tid < 48) { t = tid - 32; K = 15; w = w12 + c * 15; }
        else if (tid < 80) { t = tid - 48; K = 31; w = w21 + c * 31; }
        else               { t = tid - 80; K = 31; w = w22 + c * 31; }
        sm[PB_OFF + 2 * tid]     = (t < K) ? __ldg(w + t)     : 0.0f;
        sm[PB_OFF + 2 * tid + 1] = (t > 0) ? __ldg(w + t - 1) : 0.0f;
    } else if (tid < 142) {
        // 5x5 table, col-major conv: for dx (horizontal tap), vertical pairs
        // P5[dx][t] = (w[t][dx], w[t-1][dx]), w row-major in w0[c*25 + row*5 + col]
        const int j = tid - 112, dx = j / 6, t = j % 6;
        const float* w = w0 + c * 25 + dx;
        sm[P5_OFF + 2 * j]     = (t < 5) ? __ldg(w + t * 5)       : 0.0f;
        sm[P5_OFF + 2 * j + 1] = (t > 0) ? __ldg(w + (t - 1) * 5) : 0.0f;
    } else if (tid < 149) {                              // bias pairs
        const int j = tid - 142;
        const float* bp = (j == 0) ? b0 : (j == 1) ? b01 : (j == 2) ? b02
                        : (j == 3) ? b11 : (j == 4) ? b12 : (j == 5) ? b21 : b22;
        const float v = __ldg(bp + c);
        sm[BB_OFF + 2 * j] = v; sm[BB_OFF + 2 * j + 1] = v;
    }
    __syncthreads();

    // ====== P1: 5x5 depthwise conv, COL-MAJOR: thread = col, 16 rows.  =============
    // Outputs land in (row, col) orientation with lanes = consecutive cols, so attn
    // section 1 is stored DIRECTLY to global (coalesced STG) — no smem copy phase.
    {
        ull acc2[8];
        const ull bias2 = ldpair(sm + BB_OFF);
#pragma unroll
        for (int q = 0; q < 8; q++) acc2[q] = bias2;
        const int col = h;         // lane-contiguous
        const int r0  = col0;      // 16-row slab
#pragma unroll
        for (int dx = 0; dx < 5; dx++) {
            ull w2[6];
            loadpairs<6>(w2, sm + P5_OFF + dx * 12);
            // window row i lives at padded s_x row r0+i; horizontal tap dx-2 at col+dx
            const float* swin = s_x + r0 * SX_STRIDE + col + dx;
            conv16_reg<6>(acc2, w2, [&](int m) { return swin[m * SX_STRIDE]; });
        }
        float* sa   = s_a + 15 + col;
        float* out1 = outb + 128 * 4096 + col;
#pragma unroll
        for (int q = 0; q < 8; q++) {
            const float2 v = up2(acc2[q]);
            sa[(r0 + 2 * q) * SA_STRIDE]       = v.x;   // CF STS (lane stride 1)
            sa[(r0 + 2 * q + 1) * SA_STRIDE]   = v.y;
            out1[(r0 + 2 * q) * 64]            = v.x;   // coalesced STG
            out1[(r0 + 2 * q + 1) * 64]        = v.y;
        }
    }
    __syncthreads();   // 5x5 done; s_x (union) now dead => s_t region writable

    const float* PB = sm + PB_OFF;
    const float* BB = sm + BB_OFF;

    // ================= P2: s_t pad zero + h7 -> s_t =================================
    {
        // zero the 30 pad rows of s_t once (persist: h-stores touch rows 0..63 only)
        for (int i = tid; i < 30 * ST_STRIDE; i += THREADS) {
            const int r = i / ST_STRIDE, cc = i % ST_STRIDE;
            s_t[((r < 15) ? (r - 15) : (r + 49)) * ST_STRIDE + cc] = 0.0f;
        }
        hbranch<7>(s_a, s_t, PB + 0, ldpair(BB + 2), h, col0);
    }
    __syncthreads();

    // ================= P3..P6: v/h ladder ===========================================
    vbranch<7>(s_t, PB + 16, ldpair(BB + 4), outb + 2 * 128 * 4096, h, col0);
    __syncthreads();
    hbranch<15>(s_a, s_t, PB + 32, ldpair(BB + 6), h, col0);
    __syncthreads();
    vbranch<15>(s_t, PB + 64, ldpair(BB + 8), outb + 3 * 128 * 4096, h, col0);
    __syncthreads();
    hbranch<31>(s_a, s_t, PB + 96, ldpair(BB + 10), h, col0);
    __syncthreads();
    vbranch<31>(s_t, PB + 160, ldpair(BB + 12), outb + 4 * 128 * 4096, h, col0);
}

extern "C" void kernel_launch(void* const* d_in, const int* in_sizes, int n_in,
                              void* d_out, int out_size)
{
    constexpr int SMEM_BYTES = SMEM_FLOATS * 4;   // 49960 B > 48 KB => opt-in
    static int attr_done = 0;                     // idempotent attribute set (not a stream op)
    if (!attr_done) {
        cudaFuncSetAttribute(lka_kernel, cudaFuncAttributeMaxDynamicSharedMemorySize, SMEM_BYTES);
        attr_done = 1;
    }
    lka_kernel<<<32 * 128, THREADS, SMEM_BYTES>>>(
        (const float*)d_in[0],
        (const float*)d_in[1],  (const float*)d_in[2],
        (const float*)d_in[3],  (const float*)d_in[4],
        (const float*)d_in[5],  (const float*)d_in[6],
        (const float*)d_in[7],  (const float*)d_in[8],
        (const float*)d_in[9],  (const float*)d_in[10],
        (const float*)d_in[11], (const float*)d_in[12],
        (const float*)d_in[13], (const float*)d_in[14],
        (float*)d_out);
}

// round 14
// speedup vs baseline: 1.0603x; 1.0181x over previous
#include <cuda_runtime.h>

#define THREADS 128
using ull = unsigned long long;

// ---- strides chosen so every hot LDS/STS is bank-conflict-free ----
constexpr int SA_STRIDE = 95, SA_SIZE = 64 * 95;   // attn plane (odd stride)
constexpr int SX_STRIDE = 69, SX_SIZE = 68 * 69;   // x plane, pad 2 (odd stride)
constexpr int ST_STRIDE = 66;                      // even (==2 mod 4): STS.64 CF, col reads CF
constexpr int ST_FULL   = 94 * ST_STRIDE;          // rows -15..78 zero-padded: 6204
constexpr int UNION_SIZE  = (SX_SIZE > ST_FULL ? SX_SIZE : ST_FULL);      // 6204
constexpr int DATA_FLOATS = SA_SIZE + UNION_SIZE;  // 12284 (mult of 4 => tables 16B-aligned)
constexpr int P5_OFF = DATA_FLOATS;                // 5 dx-cols x 6 vertical pairs = 60 floats
constexpr int PB_OFF = P5_OFF + 60;                // branch pair tables: 112 pairs = 224 floats
constexpr int BB_OFF = PB_OFF + 224;               // 7 bias pairs = 14 floats
constexpr int SMEM_FLOATS = BB_OFF + 14;           // 12582 floats = 50328 B (dynamic smem)

// pair-table float offsets within PB: H7=0, V7=16, H15=32, V15=64, H31=96, V31=160

__device__ __forceinline__ ull ldpair(const float* p) { return *(const ull*)p; }
__device__ __forceinline__ void fma2(ull& acc, ull a, ull b) {
    asm("fma.rn.f32x2 %0, %1, %2, %0;" : "+l"(acc) : "l"(a), "l"(b));
}
__device__ __forceinline__ float2 up2(ull d) {
    float2 r; asm("mov.b64 {%0, %1}, %2;" : "=f"(r.x), "=f"(r.y) : "l"(d)); return r;
}
__device__ __forceinline__ ull dup(float v) {
    ull d; asm("mov.b64 %0, {%1, %1};" : "=l"(d) : "f"(v)); return d;
}

// Preload NP weight pairs (NP even) with LDS.128 broadcast: 2 pairs per instruction.
template<int NP>
__device__ __forceinline__ void loadpairs(ull* w2, const float* __restrict__ ptab) {
#pragma unroll
    for (int t = 0; t < NP; t += 2) {
        const ulonglong2 p = *(const ulonglong2*)(ptab + 2 * t);
        w2[t] = p.x; w2[t + 1] = p.y;
    }
}

// 32-output sliding window over taps [T0,T1), weights register-resident.
// acc2[q] = (out_{2q}, out_{2q+1}), q=0..15; tap pair t feeds q at step m = t + 2q.
// MB independent window loads batched per group (real MLP with the 128-reg budget).
template<int T0, int T1, int MB, class LD>
__device__ __forceinline__ void sweep32(ull acc2[16], const ull* w2, LD ld)
{
    constexpr int ME = T1 + 30;      // steps m = T0 .. ME-1
#pragma unroll
    for (int m0 = T0; m0 < ME; m0 += MB) {
        float v[MB];
#pragma unroll
        for (int u = 0; u < MB; u++)
            if (m0 + u < ME) v[u] = ld(m0 + u);
#pragma unroll
        for (int u = 0; u < MB; u++) {
            const int m = m0 + u;
            if (m < ME) {
                const ull vv = dup(v[u]);
#pragma unroll
                for (int q = 0; q < 16; q++) {
                    const int t = m - 2 * q;
                    if (t >= T0 && t < T1) fma2(acc2[q], vv, w2[t - T0]);
                }
            }
        }
    }
}

template<int K, class LD>
__device__ __forceinline__ void runconv32(ull acc2[16], const float* __restrict__ ptab, LD ld)
{
    if constexpr (K == 31) {
        ull w2[32];                      // full preload: 64 regs, fits 128-reg budget
        loadpairs<32>(w2, ptab);
        sweep32<0, 32, 4>(acc2, w2, ld);
    } else {
        ull w2[K + 1];
        loadpairs<K + 1>(w2, ptab);
        sweep32<0, K + 1, 8>(acc2, w2, ld);
    }
}

// Horizontal 1xK: s_a -> s_t. Thread: row = tid&63, 32 cols from c0. STS.64 stores (CF).
template<int K>
__device__ __forceinline__ void hbranch(const float* __restrict__ s_a,
                                        float* __restrict__ s_t,
                                        const float* __restrict__ ptab,
                                        ull bias2, int row, int c0)
{
    ull acc2[16];
#pragma unroll
    for (int q = 0; q < 16; q++) acc2[q] = bias2;
    const float* sr = s_a + row * SA_STRIDE + 15 + c0 - K / 2;
    runconv32<K>(acc2, ptab, [&](int m) { return sr[m]; });
    float2* st = (float2*)(s_t + row * ST_STRIDE + c0);   // even addr => 8B aligned
#pragma unroll
    for (int q = 0; q < 16; q++) st[q] = up2(acc2[q]);
}

// Vertical Kx1: s_t (zero-padded rows) -> global. Thread: col = tid&63, 32 rows from r0.
template<int K>
__device__ __forceinline__ void vbranch(const float* __restrict__ s_t,
                                        const float* __restrict__ ptab,
                                        ull bias2,
                                        float* __restrict__ osec, int col, int r0)
{
    ull acc2[16];
#pragma unroll
    for (int q = 0; q < 16; q++) acc2[q] = bias2;
    const float* sv = s_t + (r0 - K / 2) * ST_STRIDE + col;   // rows >= -15: in pad
    runconv32<K>(acc2, ptab, [&](int m) { return sv[m * ST_STRIDE]; });
#pragma unroll
    for (int q = 0; q < 16; q++) {
        const float2 v = up2(acc2[q]);
        osec[(r0 + 2 * q) * 64 + col] = v.x;
        osec[(r0 + 2 * q + 1) * 64 + col] = v.y;
    }
}

__global__ __launch_bounds__(THREADS, 4)   // 512 thr/SM => 128 regs/thread budget
void lka_kernel(const float* __restrict__ x,
                const float* __restrict__ w0,  const float* __restrict__ b0,
                const float* __restrict__ w01, const float* __restrict__ b01,
                const float* __restrict__ w02, const float* __restrict__ b02,
                const float* __restrict__ w11, const float* __restrict__ b11,
                const float* __restrict__ w12, const float* __restrict__ b12,
                const float* __restrict__ w21, const float* __restrict__ b21,
                const float* __restrict__ w22, const float* __restrict__ b22,
                float* __restrict__ out)
{
    extern __shared__ __align__(16) float sm[];
    float* s_a = sm;
    float* s_x = sm + SA_SIZE;                      // union
    float* s_t = sm + SA_SIZE + 15 * ST_STRIDE;     // union, rows -15..78 padded

    const int tid = threadIdx.x;
    const int bc  = blockIdx.x;
    const int c   = bc & 127;
    const int b   = bc >> 7;

    const int lane64 = tid & 63;            // row for h-passes / col for v & 5x5
    const int half32 = (tid >> 6) << 5;     // 0 or 32: col block (h) / row block (v, 5x5)

    const float* xp = x + (long)bc * 4096;
    float* outb = out + (long)b * (640 * 4096) + (long)c * 4096;

    // ================= P0: x fill + s_a/s_x margins + weight tables =================
    {
        const float4* xp4 = (const float4*)xp;
        float4* out4 = (float4*)outb;
#pragma unroll
        for (int k = 0; k < 8; k++) {
            const int i4 = tid + k * THREADS;
            const float4 v = xp4[i4];
            out4[i4] = v;
            const int i = i4 << 2;
            float* dst = &s_x[((i >> 6) + 2) * SX_STRIDE + (i & 63) + 2];
            dst[0] = v.x; dst[1] = v.y; dst[2] = v.z; dst[3] = v.w;
        }
    }
    for (int i = tid; i < 2048; i += THREADS) {          // s_a cols [0,16) U [79,95)
        const int r = i >> 5, m = i & 31;
        s_a[r * SA_STRIDE + (m < 16 ? m : 63 + m)] = 0.0f;
    }
    for (int i = tid; i < 276; i += THREADS) {           // s_x rows {0,1,66,67}
        const int r = i / 69, cc = i % 69;
        s_x[(r < 2 ? r : 64 + r) * SX_STRIDE + cc] = 0.0f;
    }
    for (int i = tid; i < 320; i += THREADS) {           // s_x cols {0,1,66,67,68}, rows [2,66)
        const int r = 2 + i / 5, cc5 = i % 5;
        s_x[r * SX_STRIDE + (cc5 < 2 ? cc5 : 64 + cc5)] = 0.0f;
    }
    if (tid < 112) {                                     // branch pair tables P[t]=(w_t,w_{t-1})
        int t; int K; const float* w;
        if (tid < 8)       { t = tid;      K = 7;  w = w01 + c * 7;  }
        else if (tid < 16) { t = tid - 8;  K = 7;  w = w02 + c * 7;  }
        else if (tid < 32) { t = tid - 16; K = 15; w = w11 + c * 15; }
        else if (tid < 48) { t = tid - 32; K = 15; w = w12 + c * 15; }
        else if (tid < 80) { t = tid - 48; K = 31; w = w21 + c * 31; }
        else               { t = tid - 80; K = 31; w = w22 + c * 31; }
        sm[PB_OFF + 2 * tid]     = (t < K) ? __ldg(w + t)     : 0.0f;
        sm[PB_OFF + 2 * tid + 1] = (t > 0) ? __ldg(w + t - 1) : 0.0f;
    }
    if (tid < 30) {
        // 5x5 table (col-major conv): P5[dx][t] = (w[t][dx], w[t-1][dx])
        const int dx = tid / 6, t = tid % 6;
        const float* w = w0 + c * 25 + dx;
        sm[P5_OFF + 2 * tid]     = (t < 5) ? __ldg(w + t * 5)       : 0.0f;
        sm[P5_OFF + 2 * tid + 1] = (t > 0) ? __ldg(w + (t - 1) * 5) : 0.0f;
    }
    if (tid >= 112 && tid < 119) {                       // bias pairs
        const int j = tid - 112;
        const float* bp = (j == 0) ? b0 : (j == 1) ? b01 : (j == 2) ? b02
                        : (j == 3) ? b11 : (j == 4) ? b12 : (j == 5) ? b21 : b22;
        const float v = __ldg(bp + c);
        sm[BB_OFF + 2 * j] = v; sm[BB_OFF + 2 * j + 1] = v;
    }
    __syncthreads();

    // ====== P1: 5x5 depthwise conv, col-major: thread = col, 32 rows. ==============
    // Direct coalesced STG of attn section + CF STS into s_a.
    {
        ull acc2[16];
        const ull bias2 = ldpair(sm + BB_OFF);
#pragma unroll
        for (int q = 0; q < 16; q++) acc2[q] = bias2;
        const int col = lane64;
        const int r0  = half32;
#pragma unroll
        for (int dx = 0; dx < 5; dx++) {
            ull w2[6];
            loadpairs<6>(w2, sm + P5_OFF + dx * 12);
            const float* swin = s_x + r0 * SX_STRIDE + col + dx;
            sweep32<0, 6, 8>(acc2, w2, [&](int m) { return swin[m * SX_STRIDE]; });
        }
        float* sa   = s_a + 15 + col;
        float* out1 = outb + 128 * 4096 + col;
#pragma unroll
        for (int q = 0; q < 16; q++) {
            const float2 v = up2(acc2[q]);
            sa[(r0 + 2 * q) * SA_STRIDE]     = v.x;   // CF STS (lane stride 1)
            sa[(r0 + 2 * q + 1) * SA_STRIDE] = v.y;
            out1[(r0 + 2 * q) * 64]          = v.x;   // coalesced STG
            out1[(r0 + 2 * q + 1) * 64]      = v.y;
        }
    }
    __syncthreads();   // 5x5 done; s_x (union) now dead => s_t region writable

    const float* PB = sm + PB_OFF;
    const float* BB = sm + BB_OFF;

    // ================= P2: s_t pad zero + h7 -> s_t =================================
    {
        for (int i = tid; i < 30 * ST_STRIDE; i += THREADS) {
            const int r = i / ST_STRIDE, cc = i % ST_STRIDE;
            s_t[((r < 15) ? (r - 15) : (r + 49)) * ST_STRIDE + cc] = 0.0f;
        }
        hbranch<7>(s_a, s_t, PB + 0, ldpair(BB + 2), lane64, half32);
    }
    __syncthreads();

    // ================= P3..P6: v/h ladder ===========================================
    vbranch<7>(s_t, PB + 16, ldpair(BB + 4), outb + 2 * 128 * 4096, lane64, half32);
    __syncthreads();
    hbranch<15>(s_a, s_t, PB + 32, ldpair(BB + 6), lane64, half32);
    __syncthreads();
    vbranch<15>(s_t, PB + 64, ldpair(BB + 8), outb + 3 * 128 * 4096, lane64, half32);
    __syncthreads();
    hbranch<31>(s_a, s_t, PB + 96, ldpair(BB + 10), lane64, half32);
    __syncthreads();
    vbranch<31>(s_t, PB + 160, ldpair(BB + 12), outb + 4 * 128 * 4096, lane64, half32);
}

extern "C" void kernel_launch(void* const* d_in, const int* in_sizes, int n_in,
                              void* d_out, int out_size)
{
    constexpr int SMEM_BYTES = SMEM_FLOATS * 4;   // 50328 B > 48 KB => opt-in
    static int attr_done = 0;                     // idempotent attribute set (not a stream op)
    if (!attr_done) {
        cudaFuncSetAttribute(lka_kernel, cudaFuncAttributeMaxDynamicSharedMemorySize, SMEM_BYTES);
        attr_done = 1;
    }
    lka_kernel<<<32 * 128, THREADS, SMEM_BYTES>>>(
        (const float*)d_in[0],
        (const float*)d_in[1],  (const float*)d_in[2],
        (const float*)d_in[3],  (const float*)d_in[4],
        (const float*)d_in[5],  (const float*)d_in[6],
        (const float*)d_in[7],  (const float*)d_in[8],
        (const float*)d_in[9],  (const float*)d_in[10],
        (const float*)d_in[11], (const float*)d_in[12],
        (const float*)d_in[13], (const float*)d_in[14],
        (float*)d_out);
}